// round 15
// baseline (speedup 1.0000x reference)
#include <cuda_runtime.h>
#include <cuda_bf16.h>
#include <stdint.h>
#include <math.h>

#define C_DIM 256
#define CQK   32
#define NVOX  4096
#define BATCH 4

// bf16 scratch + flags (static device globals; no allocation anywhere)
__device__ __nv_bfloat16 g_q[BATCH * NVOX * CQK];    // [b][n][cqk] (pre-scaled by log2e)
__device__ __nv_bfloat16 g_k[BATCH * NVOX * CQK];    // [b][m][cqk]
__device__ __nv_bfloat16 g_v[BATCH * NVOX * C_DIM];  // [b][m][c]  (row-major)
__device__ int g_flag[BATCH * 32];                   // tile-ready flags

#define LOG2E 1.4426950408889634f

// ---------------------------------------------------------------------------
// Common PTX helpers
// ---------------------------------------------------------------------------
__device__ __forceinline__ void hmma16816(float* c, const uint32_t* a,
                                          uint32_t b0, uint32_t b1)
{
    asm volatile(
        "mma.sync.aligned.m16n8k16.row.col.f32.bf16.bf16.f32 "
        "{%0,%1,%2,%3}, {%4,%5,%6,%7}, {%8,%9}, {%0,%1,%2,%3};"
        : "+f"(c[0]), "+f"(c[1]), "+f"(c[2]), "+f"(c[3])
        : "r"(a[0]), "r"(a[1]), "r"(a[2]), "r"(a[3]), "r"(b0), "r"(b1));
}
__device__ __forceinline__ void ldsm4(uint32_t* r, uint32_t addr) {
    asm volatile("ldmatrix.sync.aligned.m8n8.x4.shared.b16 {%0,%1,%2,%3}, [%4];"
                 : "=r"(r[0]), "=r"(r[1]), "=r"(r[2]), "=r"(r[3]) : "r"(addr));
}
__device__ __forceinline__ void ldsm4t(uint32_t* r, uint32_t addr) {
    asm volatile("ldmatrix.sync.aligned.m8n8.x4.trans.shared.b16 {%0,%1,%2,%3}, [%4];"
                 : "=r"(r[0]), "=r"(r[1]), "=r"(r[2]), "=r"(r[3]) : "r"(addr));
}
__device__ __forceinline__ void ldsm2t(uint32_t* r, uint32_t addr) {
    asm volatile("ldmatrix.sync.aligned.m8n8.x2.trans.shared.b16 {%0,%1}, [%2];"
                 : "=r"(r[0]), "=r"(r[1]) : "r"(addr));
}
__device__ __forceinline__ float ex2f(float x) {
    float y;
    asm("ex2.approx.ftz.f32 %0, %1;" : "=f"(y) : "f"(x));
    return y;
}
__device__ __forceinline__ void cpa16(uint32_t dst, const void* src) {
    asm volatile("cp.async.cg.shared.global [%0], [%1], 16;"
                 :: "r"(dst), "l"(src));
}
#define CPA_COMMIT() asm volatile("cp.async.commit_group;" ::: "memory")
#define CPA_WAIT(n)  asm volatile("cp.async.wait_group %0;" :: "n"(n) : "memory")
__device__ __forceinline__ uint32_t smem_u32(const void* p) {
    uint32_t a;
    asm("{ .reg .u64 t; cvta.to.shared.u64 t, %1; cvt.u32.u64 %0, t; }"
        : "=r"(a) : "l"(p));
    return a;
}

// Wait until tile t of batch b has been produced (flag set with release).
__device__ __forceinline__ void wait_tile(int b, int t) {
    if (threadIdx.x == 0) {
        volatile int* f = &g_flag[b * 32 + t];
        while (*f == 0) { }
        __threadfence();   // acquire: producer's data writes now visible
    }
    __syncthreads();       // propagate visibility to the whole block
}

// ===========================================================================
// Layout constants
// ===========================================================================
// proj phase smem
#define WT_OFF   0                       // Wt [320][72] bf16 = 46080 B
#define XS_OFF   46080                   // xs [64][136] bf16 = 17408 B
#define BS_OFF   83968                   // bs [320] float = 1280 B
#define STG_P    328                     // stage pitch (elems)
// attn phase smem
#define KP_B  80
#define VP_B  528
#define KS_BYTES (128 * KP_B)            // 10240
#define VT_BYTES (128 * VP_B)            // 67584
#define BUF_BYTES (KS_BYTES + VT_BYTES)  // 77824
#define P_OFF   (2 * BUF_BYTES)          // 155648
#define PP_B    272
#define P_BYTES (128 * PP_B)             // 34816
#define LSP_OFF (P_OFF + P_BYTES)        // 190464
#define FUSED_SMEM (LSP_OFF + 1024)      // 191488 (covers proj's 85248 too)
#define OT_PITCH 132

// ===========================================================================
// Fused kernel: phase 1 = projection for this CTA's 128 voxels (all 320 out
// rows), flag release; phase 2 = attention with per-tile flag-gated cp.async.
// Grid 32 x 4 = 128 CTAs, all co-resident (1/SM).
// ===========================================================================
__global__ __launch_bounds__(512, 1) void fused_kernel(
    const float* __restrict__ x,
    const float* __restrict__ Wq, const float* __restrict__ bq,
    const float* __restrict__ Wk, const float* __restrict__ bk,
    const float* __restrict__ Wv, const float* __restrict__ bv,
    float* __restrict__ out)
{
    extern __shared__ __align__(16) char smem[];
    const uint32_t sbase = smem_u32(smem);

    const int tid  = threadIdx.x;
    const int lane = tid & 31;
    const int w    = tid >> 5;
    const int g    = lane >> 2;
    const int tig  = lane & 3;

    const int t  = blockIdx.x;           // voxel tile 0..31
    const int b  = blockIdx.y;
    const int n0 = t * 128;

    // reset own flag (hygiene across graph replays; see launch-identical-data note)
    if (tid == 0) g_flag[b * 32 + t] = 0;

    // =======================================================================
    // PHASE 1: projection (R12 proj_kernel body)
    // =======================================================================
    {
        __nv_bfloat16* Wt = (__nv_bfloat16*)(smem + WT_OFF);
        __nv_bfloat16* xs = (__nv_bfloat16*)(smem + XS_OFF);
        float* bs = (float*)(smem + BS_OFF);
        const uint32_t wbase = smem_u32(Wt);
        const uint32_t xbase = smem_u32(xs);

        const int mg = w >> 2;   // m-group: 80 out rows
        const int nq = w & 3;    // n-quarter: 32 voxels

        const float* xb = x + (size_t)b * C_DIM * NVOX;

        for (int i = tid; i < 320; i += 512) {
            bs[i] = (i < CQK) ? bq[i] : (i < 2 * CQK) ? bk[i - CQK] : bv[i - 2 * CQK];
        }

        float acc[5][4][4];
#pragma unroll
        for (int mt = 0; mt < 5; mt++)
#pragma unroll
            for (int nt = 0; nt < 4; nt++)
#pragma unroll
                for (int q = 0; q < 4; q++) acc[mt][nt][q] = 0.f;

        for (int kc = 0; kc < 4; kc++) {
            __syncthreads();
#pragma unroll
            for (int i = 0; i < 10; i++) {
                int idx = tid + i * 512;
                int o = idx >> 4, k4 = idx & 15;
                const float* wrow = (o < CQK) ? Wq + (size_t)o * C_DIM
                                  : (o < 2 * CQK) ? Wk + (size_t)(o - CQK) * C_DIM
                                  : Wv + (size_t)(o - 2 * CQK) * C_DIM;
                float4 v = *(const float4*)(wrow + kc * 64 + k4 * 4);
                __nv_bfloat162 h0 = __float22bfloat162_rn(make_float2(v.x, v.y));
                __nv_bfloat162 h1 = __float22bfloat162_rn(make_float2(v.z, v.w));
                *(__nv_bfloat162*)(Wt + o * 72 + k4 * 4)     = h0;
                *(__nv_bfloat162*)(Wt + o * 72 + k4 * 4 + 2) = h1;
            }
#pragma unroll
            for (int i = 0; i < 4; i++) {
                int idx = tid + i * 512;
                int kr = idx >> 5, c4 = idx & 31;
                float4 v = *(const float4*)(xb + (size_t)(kc * 64 + kr) * NVOX + n0 + c4 * 4);
                __nv_bfloat162 h0 = __float22bfloat162_rn(make_float2(v.x, v.y));
                __nv_bfloat162 h1 = __float22bfloat162_rn(make_float2(v.z, v.w));
                *(__nv_bfloat162*)(xs + kr * 136 + c4 * 4)     = h0;
                *(__nv_bfloat162*)(xs + kr * 136 + c4 * 4 + 2) = h1;
            }
            __syncthreads();

#pragma unroll
            for (int kh = 0; kh < 2; kh++) {
#pragma unroll
                for (int kk = 0; kk < 2; kk++) {
                    uint32_t af[5][4];
#pragma unroll
                    for (int mt = 0; mt < 5; mt++) {
                        int row = mg * 80 + mt * 16 + (lane & 15);
                        int col16 = kh * 4 + kk * 2 + (lane >> 4);
                        ldsm4(af[mt], wbase + (uint32_t)(row * 144 + col16 * 16));
                    }
#pragma unroll
                    for (int nt = 0; nt < 4; nt++) {
                        uint32_t xf[2];
                        int krow = kh * 32 + kk * 16 + (lane & 15);
                        ldsm2t(xf, xbase + (uint32_t)(krow * 272 + (nq * 32 + nt * 8) * 2));
#pragma unroll
                        for (int mt = 0; mt < 5; mt++)
                            hmma16816(acc[mt][nt], af[mt], xf[0], xf[1]);
                    }
                }
            }
        }
        __syncthreads();

        // stage transposed: stage[n(128)][r(320)] bf16, pitch STG_P
        __nv_bfloat16* st = (__nv_bfloat16*)smem;
#pragma unroll
        for (int mt = 0; mt < 5; mt++) {
            const int ra = mg * 80 + mt * 16 + g;
            const int rb = ra + 8;
            const float ba  = bs[ra], bb2 = bs[rb];
            const float sca = (ra < CQK) ? LOG2E : 1.f;
            const float scb = (rb < CQK) ? LOG2E : 1.f;
#pragma unroll
            for (int nt = 0; nt < 4; nt++) {
                const int c0 = nq * 32 + nt * 8 + 2 * tig;
                st[(c0    ) * STG_P + ra] = __float2bfloat16((acc[mt][nt][0] + ba) * sca);
                st[(c0 + 1) * STG_P + ra] = __float2bfloat16((acc[mt][nt][1] + ba) * sca);
                st[(c0    ) * STG_P + rb] = __float2bfloat16((acc[mt][nt][2] + bb2) * scb);
                st[(c0 + 1) * STG_P + rb] = __float2bfloat16((acc[mt][nt][3] + bb2) * scb);
            }
        }
        __syncthreads();

        // coalesced gmem stores
        {
            int n = tid >> 2, ch = tid & 3;
            uint4 qv = *(const uint4*)(st + n * STG_P + ch * 8);
            uint4 kv = *(const uint4*)(st + n * STG_P + 32 + ch * 8);
            size_t base = ((size_t)b * NVOX + n0 + n) * CQK + ch * 8;
            *(uint4*)(g_q + base) = qv;
            *(uint4*)(g_k + base) = kv;
        }
#pragma unroll
        for (int i = 0; i < 8; i++) {
            int idx = tid + i * 512;
            int n = idx >> 5, ch = idx & 31;
            uint4 vv = *(const uint4*)(st + n * STG_P + 64 + ch * 8);
            *(uint4*)(g_v + ((size_t)b * NVOX + n0 + n) * C_DIM + ch * 8) = vv;
        }
    }

    // publish this tile
    __syncthreads();
    if (tid == 0) {
        __threadfence();                 // release: data before flag
        g_flag[b * 32 + t] = 1;
    }

    // =======================================================================
    // PHASE 2: attention (R12 attn_kernel body + per-tile flag gates)
    // =======================================================================
    const uint32_t pbase = sbase + P_OFF;
    const int rg = w >> 1;
    const int cs = w & 1;

    const __nv_bfloat16* qb = g_q + (size_t)b * NVOX * CQK;
    const __nv_bfloat16* kb = g_k + (size_t)b * NVOX * CQK;
    const __nv_bfloat16* vb = g_v + (size_t)b * NVOX * C_DIM;

    uint32_t qa[2][4];
    {
        const int r0 = n0 + rg * 16 + g;
#pragma unroll
        for (int kt = 0; kt < 2; kt++) {
            const int cb = kt * 16 + 2 * tig;
            qa[kt][0] = *(const uint32_t*)(qb + (size_t)r0 * CQK + cb);
            qa[kt][1] = *(const uint32_t*)(qb + (size_t)(r0 + 8) * CQK + cb);
            qa[kt][2] = *(const uint32_t*)(qb + (size_t)r0 * CQK + cb + 8);
            qa[kt][3] = *(const uint32_t*)(qb + (size_t)(r0 + 8) * CQK + cb + 8);
        }
    }

    float oacc[16][4];
#pragma unroll
    for (int j = 0; j < 16; j++)
#pragma unroll
        for (int q = 0; q < 4; q++) oacc[j][q] = 0.f;

    float ls0 = 0.f, ls1 = 0.f;

    auto issue_tile = [&](int buf, int m0) {
        const uint32_t kdst = sbase + buf * BUF_BYTES;
        const uint32_t vdst = kdst + KS_BYTES;
        {
            int r = tid >> 2, c = tid & 3;
            cpa16(kdst + r * KP_B + c * 16, kb + (size_t)(m0 + r) * CQK + c * 8);
        }
#pragma unroll
        for (int i = 0; i < 8; i++) {
            int idx = tid + i * 512;
            int r = idx >> 5, c = idx & 31;
            cpa16(vdst + r * VP_B + c * 16, vb + (size_t)(m0 + r) * C_DIM + c * 8);
        }
        CPA_COMMIT();
    };

    wait_tile(b, 0);
    issue_tile(0, 0);

    const int l8 = lane & 7, l8g = lane >> 3;
    const int prow_a = rg * 16 + g;
    const uint32_t pA = pbase + (uint32_t)((rg * 16 + (lane & 15)) * PP_B
                                           + (lane >> 4) * 16);

    for (int it = 0; it < 32; ++it) {
        if (it + 1 < 32) {
            wait_tile(b, it + 1);
            issue_tile((it + 1) & 1, (it + 1) * 128);
        }
        if (it + 1 < 32) { CPA_WAIT(1); } else { CPA_WAIT(0); }
        __syncthreads();

        const uint32_t ksb = sbase + (it & 1) * BUF_BYTES;
        const uint32_t vtb = ksb + KS_BYTES;

#pragma unroll
        for (int cc = 0; cc < 2; cc++) {
            float sacc[4][4];
#pragma unroll
            for (int jj = 0; jj < 4; jj++) {
                const int j = cs * 8 + cc * 4 + jj;
#pragma unroll
                for (int q = 0; q < 4; q++) sacc[jj][q] = 0.f;
                uint32_t kf[4];
                ldsm4(kf, ksb + (uint32_t)((8 * j + l8) * KP_B + l8g * 16));
                hmma16816(sacc[jj], qa[0], kf[0], kf[1]);
                hmma16816(sacc[jj], qa[1], kf[2], kf[3]);
            }
#pragma unroll
            for (int jj = 0; jj < 4; jj++) {
                const int j = cs * 8 + cc * 4 + jj;
                float e0 = ex2f(sacc[jj][0]);
                float e1 = ex2f(sacc[jj][1]);
                float e2 = ex2f(sacc[jj][2]);
                float e3 = ex2f(sacc[jj][3]);
                ls0 += e0 + e1;
                ls1 += e2 + e3;
                __nv_bfloat162 ha = __float22bfloat162_rn(make_float2(e0, e1));
                __nv_bfloat162 hb = __float22bfloat162_rn(make_float2(e2, e3));
                const uint32_t cbyte = (uint32_t)((j * 8 + 2 * tig) * 2);
                asm volatile("st.shared.b32 [%0], %1;"
                             :: "r"(pbase + (uint32_t)(prow_a * PP_B) + cbyte),
                                "r"(*reinterpret_cast<uint32_t*>(&ha)) : "memory");
                asm volatile("st.shared.b32 [%0], %1;"
                             :: "r"(pbase + (uint32_t)((prow_a + 8) * PP_B) + cbyte),
                                "r"(*reinterpret_cast<uint32_t*>(&hb)) : "memory");
            }
        }

        asm volatile("bar.sync %0, 64;" :: "r"(rg + 1) : "memory");

#pragma unroll
        for (int q = 0; q < 4; q++) {
            uint32_t pa0[4], pa1[4];
            ldsm4(pa0, pA + (uint32_t)((4 * q    ) * 16));
            ldsm4(pa1, pA + (uint32_t)((4 * q + 2) * 16));
#pragma unroll
            for (int j = 0; j < 16; j++) {
                uint32_t vf[4];
                ldsm4t(vf, vtb + (uint32_t)((q * 32 + lane) * VP_B + (cs * 16 + j) * 16));
                hmma16816(oacc[j], pa0, vf[0], vf[1]);
                hmma16816(oacc[j], pa1, vf[2], vf[3]);
            }
        }
        __syncthreads();
    }

    ls0 += __shfl_xor_sync(0xFFFFFFFFu, ls0, 1);
    ls0 += __shfl_xor_sync(0xFFFFFFFFu, ls0, 2);
    ls1 += __shfl_xor_sync(0xFFFFFFFFu, ls1, 1);
    ls1 += __shfl_xor_sync(0xFFFFFFFFu, ls1, 2);
    float* lsp = (float*)(smem + LSP_OFF);
    if (tig == 0) {
        lsp[(rg * 2 + cs) * 16 + g]     = ls0;
        lsp[(rg * 2 + cs) * 16 + g + 8] = ls1;
    }
    __syncthreads();
    const float inv0 = 1.f / (lsp[(rg * 2) * 16 + g]     + lsp[(rg * 2 + 1) * 16 + g]);
    const float inv1 = 1.f / (lsp[(rg * 2) * 16 + g + 8] + lsp[(rg * 2 + 1) * 16 + g + 8]);

    float* Ot = (float*)smem;
#pragma unroll
    for (int j = 0; j < 16; j++) {
        const int c0 = cs * 128 + j * 8 + 2 * tig;
        const int na = rg * 16 + g;
        Ot[(c0    ) * OT_PITCH + na]     = oacc[j][0] * inv0;
        Ot[(c0 + 1) * OT_PITCH + na]     = oacc[j][1] * inv0;
        Ot[(c0    ) * OT_PITCH + na + 8] = oacc[j][2] * inv1;
        Ot[(c0 + 1) * OT_PITCH + na + 8] = oacc[j][3] * inv1;
    }
    __syncthreads();

    const float* xb2 = x + (size_t)b * C_DIM * NVOX;
    float* ob = out + (size_t)b * C_DIM * NVOX;
    for (int idx = tid; idx < 256 * 128; idx += 512) {
        int n = idx & 127, c = idx >> 7;
        size_t gg = (size_t)c * NVOX + n0 + n;
        ob[gg] = xb2[gg] + Ot[c * OT_PITCH + n];
    }
}

// ===========================================================================
extern "C" void kernel_launch(void* const* d_in, const int* in_sizes, int n_in,
                              void* d_out, int out_size)
{
    const float* x  = (const float*)d_in[0];
    const float* Wq = (const float*)d_in[1];
    const float* bq = (const float*)d_in[2];
    const float* Wk = (const float*)d_in[3];
    const float* bk = (const float*)d_in[4];
    const float* Wv = (const float*)d_in[5];
    const float* bv = (const float*)d_in[6];
    float* out = (float*)d_out;

    cudaFuncSetAttribute(fused_kernel,
                         cudaFuncAttributeMaxDynamicSharedMemorySize, FUSED_SMEM);
    fused_kernel<<<dim3(NVOX / 128, BATCH), 512, FUSED_SMEM>>>(
        x, Wq, bq, Wk, bk, Wv, bv, out);
}

// round 16
// speedup vs baseline: 1.1334x; 1.1334x over previous
#include <cuda_runtime.h>
#include <cuda_bf16.h>
#include <stdint.h>
#include <math.h>

#define C_DIM 256
#define CQK   32
#define NVOX  4096
#define BATCH 4

// bf16 scratch (static device globals; no allocation anywhere)
__device__ __nv_bfloat16 g_q[BATCH * NVOX * CQK];    // [b][n][cqk] (pre-scaled by log2e)
__device__ __nv_bfloat16 g_k[BATCH * NVOX * CQK];    // [b][m][cqk]
__device__ __nv_bfloat16 g_v[BATCH * NVOX * C_DIM];  // [b][m][c]  (row-major)

#define LOG2E 1.4426950408889634f

// ---------------------------------------------------------------------------
// Common PTX helpers
// ---------------------------------------------------------------------------
__device__ __forceinline__ void hmma16816(float* c, const uint32_t* a,
                                          uint32_t b0, uint32_t b1)
{
    asm volatile(
        "mma.sync.aligned.m16n8k16.row.col.f32.bf16.bf16.f32 "
        "{%0,%1,%2,%3}, {%4,%5,%6,%7}, {%8,%9}, {%0,%1,%2,%3};"
        : "+f"(c[0]), "+f"(c[1]), "+f"(c[2]), "+f"(c[3])
        : "r"(a[0]), "r"(a[1]), "r"(a[2]), "r"(a[3]), "r"(b0), "r"(b1));
}
__device__ __forceinline__ void ldsm4(uint32_t* r, uint32_t addr) {
    asm volatile("ldmatrix.sync.aligned.m8n8.x4.shared.b16 {%0,%1,%2,%3}, [%4];"
                 : "=r"(r[0]), "=r"(r[1]), "=r"(r[2]), "=r"(r[3]) : "r"(addr));
}
__device__ __forceinline__ void ldsm4t(uint32_t* r, uint32_t addr) {
    asm volatile("ldmatrix.sync.aligned.m8n8.x4.trans.shared.b16 {%0,%1,%2,%3}, [%4];"
                 : "=r"(r[0]), "=r"(r[1]), "=r"(r[2]), "=r"(r[3]) : "r"(addr));
}
__device__ __forceinline__ void ldsm2t(uint32_t* r, uint32_t addr) {
    asm volatile("ldmatrix.sync.aligned.m8n8.x2.trans.shared.b16 {%0,%1}, [%2];"
                 : "=r"(r[0]), "=r"(r[1]) : "r"(addr));
}
__device__ __forceinline__ float ex2f(float x) {
    float y;
    asm("ex2.approx.ftz.f32 %0, %1;" : "=f"(y) : "f"(x));
    return y;
}
__device__ __forceinline__ void cpa16(uint32_t dst, const void* src) {
    asm volatile("cp.async.cg.shared.global [%0], [%1], 16;"
                 :: "r"(dst), "l"(src));
}
#define CPA_COMMIT() asm volatile("cp.async.commit_group;" ::: "memory")
#define CPA_WAIT(n)  asm volatile("cp.async.wait_group %0;" :: "n"(n) : "memory")
__device__ __forceinline__ uint32_t smem_u32(const void* p) {
    uint32_t a;
    asm("{ .reg .u64 t; cvta.to.shared.u64 t, %1; cvt.u32.u64 %0, t; }"
        : "=r"(a) : "l"(p));
    return a;
}

// ===========================================================================
// Projection kernel: one CTA computes ALL 320 output rows for 128 voxels.
// Grid = 32 x 4 = 128 CTAs (<= 1 wave). x read ONCE. 512 threads = 16 warps
// = 4 m-groups (80 rows = 5 m16) x 4 n-quarters (32 vox = 4 n8).
// K = 256 in 4 chunks of 64 (W chunk + x chunk staged in smem as bf16).
// ===========================================================================
#define WT_OFF   0                       // Wt [320][72] bf16 = 46080 B
#define XS_OFF   46080                   // xs [64][136] bf16 = 17408 B
#define BS_OFF   83968                   // bs [320] float = 1280 B
#define STG_P    328                     // stage pitch (elems); 656 B = 41x16
#define PJ_SMEM  85248                   // stage [128][328] bf16 overlays Wt/xs

__global__ __launch_bounds__(512, 1) void proj_kernel(
    const float* __restrict__ x,
    const float* __restrict__ Wq, const float* __restrict__ bq,
    const float* __restrict__ Wk, const float* __restrict__ bk,
    const float* __restrict__ Wv, const float* __restrict__ bv)
{
    extern __shared__ __align__(16) char psm[];
    __nv_bfloat16* Wt = (__nv_bfloat16*)(psm + WT_OFF);
    __nv_bfloat16* xs = (__nv_bfloat16*)(psm + XS_OFF);
    float* bs = (float*)(psm + BS_OFF);
    const uint32_t wbase = smem_u32(Wt);
    const uint32_t xbase = smem_u32(xs);

    const int tid  = threadIdx.x;
    const int lane = tid & 31;
    const int w    = tid >> 5;
    const int g    = lane >> 2;
    const int tig  = lane & 3;
    const int mg   = w >> 2;     // m-group: 80 out rows
    const int nq   = w & 3;      // n-quarter: 32 voxels

    const int n0 = blockIdx.x * 128;
    const int b  = blockIdx.y;

    const float* xb = x + (size_t)b * C_DIM * NVOX;

    // bias table
    for (int i = tid; i < 320; i += 512) {
        bs[i] = (i < CQK) ? bq[i] : (i < 2 * CQK) ? bk[i - CQK] : bv[i - 2 * CQK];
    }

    float acc[5][4][4];
#pragma unroll
    for (int mt = 0; mt < 5; mt++)
#pragma unroll
        for (int nt = 0; nt < 4; nt++)
#pragma unroll
            for (int q = 0; q < 4; q++) acc[mt][nt][q] = 0.f;

    for (int kc = 0; kc < 4; kc++) {
        __syncthreads();
        // ---- W chunk: 320 rows x 64 k fp32 -> bf16 smem [320][72]
#pragma unroll
        for (int i = 0; i < 10; i++) {
            int idx = tid + i * 512;
            int o = idx >> 4, k4 = idx & 15;
            const float* wrow = (o < CQK) ? Wq + (size_t)o * C_DIM
                              : (o < 2 * CQK) ? Wk + (size_t)(o - CQK) * C_DIM
                              : Wv + (size_t)(o - 2 * CQK) * C_DIM;
            float4 v = *(const float4*)(wrow + kc * 64 + k4 * 4);
            __nv_bfloat162 h0 = __float22bfloat162_rn(make_float2(v.x, v.y));
            __nv_bfloat162 h1 = __float22bfloat162_rn(make_float2(v.z, v.w));
            *(__nv_bfloat162*)(Wt + o * 72 + k4 * 4)     = h0;
            *(__nv_bfloat162*)(Wt + o * 72 + k4 * 4 + 2) = h1;
        }
        // ---- x chunk: 64 k x 128 n fp32 -> bf16 smem [64][136]
#pragma unroll
        for (int i = 0; i < 4; i++) {
            int idx = tid + i * 512;
            int kr = idx >> 5, c4 = idx & 31;
            float4 v = *(const float4*)(xb + (size_t)(kc * 64 + kr) * NVOX + n0 + c4 * 4);
            __nv_bfloat162 h0 = __float22bfloat162_rn(make_float2(v.x, v.y));
            __nv_bfloat162 h1 = __float22bfloat162_rn(make_float2(v.z, v.w));
            *(__nv_bfloat162*)(xs + kr * 136 + c4 * 4)     = h0;
            *(__nv_bfloat162*)(xs + kr * 136 + c4 * 4 + 2) = h1;
        }
        __syncthreads();

        // ---- MMA: 4 k16 steps in this chunk
#pragma unroll
        for (int kh = 0; kh < 2; kh++) {
#pragma unroll
            for (int kk = 0; kk < 2; kk++) {
                uint32_t af[5][4];
#pragma unroll
                for (int mt = 0; mt < 5; mt++) {
                    int row = mg * 80 + mt * 16 + (lane & 15);
                    int col16 = kh * 4 + kk * 2 + (lane >> 4);
                    ldsm4(af[mt], wbase + (uint32_t)(row * 144 + col16 * 16));
                }
#pragma unroll
                for (int nt = 0; nt < 4; nt++) {
                    uint32_t xf[2];
                    int krow = kh * 32 + kk * 16 + (lane & 15);
                    ldsm2t(xf, xbase + (uint32_t)(krow * 272 + (nq * 32 + nt * 8) * 2));
#pragma unroll
                    for (int mt = 0; mt < 5; mt++)
                        hmma16816(acc[mt][nt], af[mt], xf[0], xf[1]);
                }
            }
        }
    }
    __syncthreads();

    // ---- stage transposed: stage[n(128)][r(320)] bf16, pitch STG_P
    __nv_bfloat16* st = (__nv_bfloat16*)psm;
#pragma unroll
    for (int mt = 0; mt < 5; mt++) {
        const int ra = mg * 80 + mt * 16 + g;
        const int rb = ra + 8;
        const float ba  = bs[ra] , bb2 = bs[rb];
        const float sca = (ra < CQK) ? LOG2E : 1.f;
        const float scb = (rb < CQK) ? LOG2E : 1.f;
#pragma unroll
        for (int nt = 0; nt < 4; nt++) {
            const int c0 = nq * 32 + nt * 8 + 2 * tig;
            st[(c0    ) * STG_P + ra] = __float2bfloat16((acc[mt][nt][0] + ba) * sca);
            st[(c0 + 1) * STG_P + ra] = __float2bfloat16((acc[mt][nt][1] + ba) * sca);
            st[(c0    ) * STG_P + rb] = __float2bfloat16((acc[mt][nt][2] + bb2) * scb);
            st[(c0 + 1) * STG_P + rb] = __float2bfloat16((acc[mt][nt][3] + bb2) * scb);
        }
    }
    __syncthreads();

    // ---- coalesced gmem stores
    {
        // q + k: 128 n x 4 chunks of 8 bf16
        int n = tid >> 2, ch = tid & 3;
        uint4 qv = *(const uint4*)(st + n * STG_P + ch * 8);
        uint4 kv = *(const uint4*)(st + n * STG_P + 32 + ch * 8);
        size_t base = ((size_t)b * NVOX + n0 + n) * CQK + ch * 8;
        *(uint4*)(g_q + base) = qv;
        *(uint4*)(g_k + base) = kv;
    }
#pragma unroll
    for (int i = 0; i < 8; i++) {
        int idx = tid + i * 512;
        int n = idx >> 5, ch = idx & 31;
        uint4 vv = *(const uint4*)(st + n * STG_P + 64 + ch * 8);
        *(uint4*)(g_v + ((size_t)b * NVOX + n0 + n) * C_DIM + ch * 8) = vv;
    }
}

// ===========================================================================
// Attention kernel: 512 threads, 16 warps = 8 row-groups x 2 C-splits;
// P shared via smem; cp.async double-buffered K/V; max-free base-2 softmax.
// At the sm_103a legacy-HMMA issue ceiling: 2304 HMMA/SM/iter x 4 cyc
// = 9216 cyc/iter floor (measured 9170-9290 across 7 variants).
// ===========================================================================
#define KP_B  80
#define VP_B  528
#define KS_BYTES (128 * KP_B)            // 10240
#define VT_BYTES (128 * VP_B)            // 67584
#define BUF_BYTES (KS_BYTES + VT_BYTES)  // 77824
#define P_OFF   (2 * BUF_BYTES)          // 155648
#define PP_B    272
#define P_BYTES (128 * PP_B)             // 34816
#define LSP_OFF (P_OFF + P_BYTES)        // 190464
#define ATTN_SMEM (LSP_OFF + 1024)       // 191488
#define OT_PITCH 132

__global__ __launch_bounds__(512, 1) void attn_kernel(
    const float* __restrict__ x, float* __restrict__ out)
{
    extern __shared__ __align__(16) char smem[];
    const uint32_t sbase = smem_u32(smem);
    const uint32_t pbase = sbase + P_OFF;

    const int tid  = threadIdx.x;
    const int w    = tid >> 5;
    const int lane = tid & 31;
    const int g    = lane >> 2;
    const int tig  = lane & 3;
    const int rg   = w >> 1;
    const int cs   = w & 1;

    const int b  = blockIdx.y;
    const int n0 = blockIdx.x * 128;

    const __nv_bfloat16* qb = g_q + (size_t)b * NVOX * CQK;
    const __nv_bfloat16* kb = g_k + (size_t)b * NVOX * CQK;
    const __nv_bfloat16* vb = g_v + (size_t)b * NVOX * C_DIM;

    uint32_t qa[2][4];
    {
        const int r0 = n0 + rg * 16 + g;
#pragma unroll
        for (int kt = 0; kt < 2; kt++) {
            const int cb = kt * 16 + 2 * tig;
            qa[kt][0] = *(const uint32_t*)(qb + (size_t)r0 * CQK + cb);
            qa[kt][1] = *(const uint32_t*)(qb + (size_t)(r0 + 8) * CQK + cb);
            qa[kt][2] = *(const uint32_t*)(qb + (size_t)r0 * CQK + cb + 8);
            qa[kt][3] = *(const uint32_t*)(qb + (size_t)(r0 + 8) * CQK + cb + 8);
        }
    }

    float oacc[16][4];
#pragma unroll
    for (int j = 0; j < 16; j++)
#pragma unroll
        for (int q = 0; q < 4; q++) oacc[j][q] = 0.f;

    float ls0 = 0.f, ls1 = 0.f;

    auto issue_tile = [&](int buf, int m0) {
        const uint32_t kdst = sbase + buf * BUF_BYTES;
        const uint32_t vdst = kdst + KS_BYTES;
        {
            int r = tid >> 2, c = tid & 3;
            cpa16(kdst + r * KP_B + c * 16, kb + (size_t)(m0 + r) * CQK + c * 8);
        }
#pragma unroll
        for (int i = 0; i < 8; i++) {
            int idx = tid + i * 512;
            int r = idx >> 5, c = idx & 31;
            cpa16(vdst + r * VP_B + c * 16, vb + (size_t)(m0 + r) * C_DIM + c * 8);
        }
        CPA_COMMIT();
    };

    issue_tile(0, 0);

    const int l8 = lane & 7, l8g = lane >> 3;
    const int prow_a = rg * 16 + g;
    const uint32_t pA = pbase + (uint32_t)((rg * 16 + (lane & 15)) * PP_B
                                           + (lane >> 4) * 16);

    for (int it = 0; it < 32; ++it) {
        if (it + 1 < 32) issue_tile((it + 1) & 1, (it + 1) * 128);
        if (it + 1 < 32) { CPA_WAIT(1); } else { CPA_WAIT(0); }
        __syncthreads();

        const uint32_t ksb = sbase + (it & 1) * BUF_BYTES;
        const uint32_t vtb = ksb + KS_BYTES;

#pragma unroll
        for (int cc = 0; cc < 2; cc++) {
            float sacc[4][4];
#pragma unroll
            for (int jj = 0; jj < 4; jj++) {
                const int j = cs * 8 + cc * 4 + jj;
#pragma unroll
                for (int q = 0; q < 4; q++) sacc[jj][q] = 0.f;
                uint32_t kf[4];
                ldsm4(kf, ksb + (uint32_t)((8 * j + l8) * KP_B + l8g * 16));
                hmma16816(sacc[jj], qa[0], kf[0], kf[1]);
                hmma16816(sacc[jj], qa[1], kf[2], kf[3]);
            }
#pragma unroll
            for (int jj = 0; jj < 4; jj++) {
                const int j = cs * 8 + cc * 4 + jj;
                float e0 = ex2f(sacc[jj][0]);
                float e1 = ex2f(sacc[jj][1]);
                float e2 = ex2f(sacc[jj][2]);
                float e3 = ex2f(sacc[jj][3]);
                ls0 += e0 + e1;
                ls1 += e2 + e3;
                __nv_bfloat162 ha = __float22bfloat162_rn(make_float2(e0, e1));
                __nv_bfloat162 hb = __float22bfloat162_rn(make_float2(e2, e3));
                const uint32_t cbyte = (uint32_t)((j * 8 + 2 * tig) * 2);
                asm volatile("st.shared.b32 [%0], %1;"
                             :: "r"(pbase + (uint32_t)(prow_a * PP_B) + cbyte),
                                "r"(*reinterpret_cast<uint32_t*>(&ha)) : "memory");
                asm volatile("st.shared.b32 [%0], %1;"
                             :: "r"(pbase + (uint32_t)((prow_a + 8) * PP_B) + cbyte),
                                "r"(*reinterpret_cast<uint32_t*>(&hb)) : "memory");
            }
        }

        asm volatile("bar.sync %0, 64;" :: "r"(rg + 1) : "memory");

#pragma unroll
        for (int q = 0; q < 4; q++) {
            uint32_t pa0[4], pa1[4];
            ldsm4(pa0, pA + (uint32_t)((4 * q    ) * 16));
            ldsm4(pa1, pA + (uint32_t)((4 * q + 2) * 16));
#pragma unroll
            for (int j = 0; j < 16; j++) {
                uint32_t vf[4];
                ldsm4t(vf, vtb + (uint32_t)((q * 32 + lane) * VP_B + (cs * 16 + j) * 16));
                hmma16816(oacc[j], pa0, vf[0], vf[1]);
                hmma16816(oacc[j], pa1, vf[2], vf[3]);
            }
        }
        __syncthreads();
    }

    ls0 += __shfl_xor_sync(0xFFFFFFFFu, ls0, 1);
    ls0 += __shfl_xor_sync(0xFFFFFFFFu, ls0, 2);
    ls1 += __shfl_xor_sync(0xFFFFFFFFu, ls1, 1);
    ls1 += __shfl_xor_sync(0xFFFFFFFFu, ls1, 2);
    float* lsp = (float*)(smem + LSP_OFF);
    if (tig == 0) {
        lsp[(rg * 2 + cs) * 16 + g]     = ls0;
        lsp[(rg * 2 + cs) * 16 + g + 8] = ls1;
    }
    __syncthreads();
    const float inv0 = 1.f / (lsp[(rg * 2) * 16 + g]     + lsp[(rg * 2 + 1) * 16 + g]);
    const float inv1 = 1.f / (lsp[(rg * 2) * 16 + g + 8] + lsp[(rg * 2 + 1) * 16 + g + 8]);

    float* Ot = (float*)smem;
#pragma unroll
    for (int j = 0; j < 16; j++) {
        const int c0 = cs * 128 + j * 8 + 2 * tig;
        const int na = rg * 16 + g;
        Ot[(c0    ) * OT_PITCH + na]     = oacc[j][0] * inv0;
        Ot[(c0 + 1) * OT_PITCH + na]     = oacc[j][1] * inv0;
        Ot[(c0    ) * OT_PITCH + na + 8] = oacc[j][2] * inv1;
        Ot[(c0 + 1) * OT_PITCH + na + 8] = oacc[j][3] * inv1;
    }
    __syncthreads();

    const float* xb = x + (size_t)b * C_DIM * NVOX;
    float* ob = out + (size_t)b * C_DIM * NVOX;
    for (int idx = tid; idx < 256 * 128; idx += 512) {
        int n = idx & 127, c = idx >> 7;
        size_t gg = (size_t)c * NVOX + n0 + n;
        ob[gg] = xb[gg] + Ot[c * OT_PITCH + n];
    }
}

// ===========================================================================
extern "C" void kernel_launch(void* const* d_in, const int* in_sizes, int n_in,
                              void* d_out, int out_size)
{
    const float* x  = (const float*)d_in[0];
    const float* Wq = (const float*)d_in[1];
    const float* bq = (const float*)d_in[2];
    const float* Wk = (const float*)d_in[3];
    const float* bk = (const float*)d_in[4];
    const float* Wv = (const float*)d_in[5];
    const float* bv = (const float*)d_in[6];
    float* out = (float*)d_out;

    cudaFuncSetAttribute(proj_kernel,
                         cudaFuncAttributeMaxDynamicSharedMemorySize, PJ_SMEM);
    proj_kernel<<<dim3(NVOX / 128, BATCH), 512, PJ_SMEM>>>(
        x, Wq, bq, Wk, bk, Wv, bv);

    cudaFuncSetAttribute(attn_kernel,
                         cudaFuncAttributeMaxDynamicSharedMemorySize, ATTN_SMEM);
    attn_kernel<<<dim3(NVOX / 128, BATCH), 512, ATTN_SMEM>>>(x, out);
}